// round 10
// baseline (speedup 1.0000x reference)
#include <cuda_runtime.h>
#include <cstdint>

// y = spikes @ V @ U^T
// spikes: [512, 32768] f32   (d_in[0])
// U     : [32768, 64]  f32   (d_in[1])
// V     : [32768, 64]  f32   (d_in[2])
// mask_* inputs unused. out: [512, 32768] f32
//
// mma.sync bf16, hi/lo split, 3 products (hi*hi + hi*lo + lo*hi).
// g2: barrier-free mainloop — U pre-packed into mma fragment order so B
// operands are direct coalesced LDG.128 (no smem, no cp.async, no syncs).
// NOTE: cp.async into a shared buffer may only be issued AFTER the
// __syncthreads() that proves all warps finished reading that buffer.

constexpr int BATCH = 512;
constexpr int NPRE  = 32768;
constexpr int NPOST = 32768;
constexpr int R     = 64;

constexpr int KSPLIT = 64;
constexpr int KCHUNK = NPRE / KSPLIT;   // 512

// ---------------- scratch (allocation-free: device globals) ----------------
__device__ __align__(16) float    g_Zpart[KSPLIT * BATCH * R];   // 8 MB
__device__ __align__(16) uint32_t g_Vh[NPRE * R / 2];            // 4 MB each
__device__ __align__(16) uint32_t g_Vl[NPRE * R / 2];
__device__ __align__(16) uint32_t g_Ufh[8192 * 128];             // 4 MB: U frag hi
__device__ __align__(16) uint32_t g_Ufl[8192 * 128];             // 4 MB: U frag lo
__device__ __align__(16) uint32_t g_Zh[BATCH * R / 2];           // 64 KB each
__device__ __align__(16) uint32_t g_Zl[BATCH * R / 2];

// ---------------- helpers ---------------------------------------------------
__device__ __forceinline__ uint32_t smem_u32(const void* p) {
    uint32_t a;
    asm("{ .reg .u64 t; cvta.to.shared.u64 t, %1; cvt.u32.u64 %0, t; }"
        : "=r"(a) : "l"(p));
    return a;
}

// cheap split: hi = round-half-up bf16 (packed via PRMT), lo = RN bf16 of
// exact residual (packed via cvt.rn.bf16x2).  elem0 in low half.
__device__ __forceinline__ void split2(float x, float y, uint32_t& hp, uint32_t& lp) {
    uint32_t vx = __float_as_uint(x) + 0x8000u;
    uint32_t vy = __float_as_uint(y) + 0x8000u;
    asm("prmt.b32 %0, %1, %2, 0x7632;" : "=r"(hp) : "r"(vx), "r"(vy));
    float lx = x - __uint_as_float(vx & 0xFFFF0000u);
    float ly = y - __uint_as_float(vy & 0xFFFF0000u);
    asm("cvt.rn.bf16x2.f32 %0, %1, %2;" : "=r"(lp) : "f"(ly), "f"(lx));
}

__device__ __forceinline__ void cp16(uint32_t dst, const void* src) {
    asm volatile("cp.async.cg.shared.global [%0], [%1], 16;"
                 :: "r"(dst), "l"(src) : "memory");
}
#define CP_COMMIT() asm volatile("cp.async.commit_group;" ::: "memory")
#define CP_WAIT0()  asm volatile("cp.async.wait_group 0;" ::: "memory")

__device__ __forceinline__ void ldm_x4(uint32_t (&r)[4], uint32_t addr) {
    asm volatile("ldmatrix.sync.aligned.m8n8.x4.shared.b16 {%0,%1,%2,%3}, [%4];"
                 : "=r"(r[0]), "=r"(r[1]), "=r"(r[2]), "=r"(r[3]) : "r"(addr));
}
__device__ __forceinline__ void ldm_x4_t(uint32_t (&r)[4], uint32_t addr) {
    asm volatile("ldmatrix.sync.aligned.m8n8.x4.trans.shared.b16 {%0,%1,%2,%3}, [%4];"
                 : "=r"(r[0]), "=r"(r[1]), "=r"(r[2]), "=r"(r[3]) : "r"(addr));
}
__device__ __forceinline__ void mma16816(float (&d)[4], const uint32_t (&a)[4],
                                         uint32_t b0, uint32_t b1) {
    asm volatile("mma.sync.aligned.m16n8k16.row.col.f32.bf16.bf16.f32 "
                 "{%0,%1,%2,%3}, {%4,%5,%6,%7}, {%8,%9}, {%0,%1,%2,%3};"
                 : "+f"(d[0]), "+f"(d[1]), "+f"(d[2]), "+f"(d[3])
                 : "r"(a[0]), "r"(a[1]), "r"(a[2]), "r"(a[3]), "r"(b0), "r"(b1));
}

// ===========================================================================
// prep A: split V into packed bf16 hi/lo buffers (k-major rows of 128B)
// ===========================================================================
__global__ void __launch_bounds__(256, 4)
split_v_kernel(const float* __restrict__ V) {
    const int gid = blockIdx.x * 256 + threadIdx.x;       // float4 index
    float4 v = ((const float4*)V)[gid];
    uint32_t h0, l0, h1, l1;
    split2(v.x, v.y, h0, l0);
    split2(v.z, v.w, h1, l1);
    ((uint2*)g_Vh)[gid] = make_uint2(h0, h1);
    ((uint2*)g_Vl)[gid] = make_uint2(l0, l1);
}

// ===========================================================================
// prep B: split U AND pack into mma b-fragment order.
// Uses the exact ldmatrix path g2 previously used, so the register mapping
// is correct by construction.  frag id = (nt*4 + n16l)*4 + s; each frag is
// 32 lanes x 4 u32 (LDG.128-able).  One block per 64-row n-tile.
// smem: Uh[64x128B]@0  Ul@8192
// ===========================================================================
__global__ void __launch_bounds__(256, 4)
prep_ufrag_kernel(const float* __restrict__ U) {
    __shared__ __align__(16) char sm[16384];
    const uint32_t sb = smem_u32(sm);
    const int tid = threadIdx.x, lane = tid & 31, w = tid >> 5;
    const int nt = blockIdx.x;

    // split-stage U tile [64 n][64 k] -> swizzled bf16 hi/lo rows of 128B
    const int r0 = tid >> 4, seg = tid & 15;
    const float* Up = U + (size_t)(nt * 64 + r0) * R + seg * 4;
#pragma unroll
    for (int i = 0; i < 4; i++) {
        int row = r0 + 16 * i;
        float4 v = *(const float4*)(Up + (size_t)i * 16 * R);
        uint32_t h0, l0, h1, l1;
        split2(v.x, v.y, h0, l0);
        split2(v.z, v.w, h1, l1);
        uint32_t off = (uint32_t)row * 128u + (((uint32_t)seg * 8u) ^ ((uint32_t)(row & 7) << 4));
        *(uint2*)(sm + off)        = make_uint2(h0, h1);
        *(uint2*)(sm + 8192 + off) = make_uint2(l0, l1);
    }
    __syncthreads();

    const uint32_t lrow  = (uint32_t)(lane & 15) * 128u;
    const uint32_t lhalf = (uint32_t)(lane >> 4) * 16u;
    const uint32_t lx    = (uint32_t)(lane & 7) << 4;

#pragma unroll
    for (int rep = 0; rep < 2; rep++) {
        int j = w + rep * 8;                 // 0..15
        int n16l = j >> 2, s = j & 3;
        uint32_t ad = sb + (uint32_t)n16l * 2048u + lrow
                    + (((uint32_t)s * 32u + lhalf) ^ lx);
        uint32_t bh[4], bl[4];
        ldm_x4(bh, ad);
        ldm_x4(bl, ad + 8192);
        uint32_t fragid = ((uint32_t)nt * 4u + n16l) * 4u + s;
        *(uint4*)(g_Ufh + fragid * 128u + lane * 4u) =
            make_uint4(bh[0], bh[1], bh[2], bh[3]);
        *(uint4*)(g_Ufl + fragid * 128u + lane * 4u) =
            make_uint4(bl[0], bl[1], bl[2], bl[3]);
    }
}

// ===========================================================================
// GEMM1: Zpart[ks][b][r] = sum_{k in chunk} spikes[b][k] * V[k][r]
// Tile 128(m) x 64(n=R), K-tile 64, 8 k-tiles, double-buffered smem.
// 8 warps = 4m x 2n, warp 32x32.
// per-buffer smem: Ah[128x64 bf16]@0 Al@16K  Bh[64k x 64n]@32K Bl@40K (48K)
// ===========================================================================
constexpr uint32_t G1_AL = 16384, G1_BH = 32768, G1_BL = 40960;
constexpr uint32_t G1_BUF = 49152;
constexpr int G1_SMEM = 98304;

__global__ void __launch_bounds__(256, 2)
g1_kernel(const float* __restrict__ S) {
    extern __shared__ char sm[];
    const uint32_t sb = smem_u32(sm);
    const int tid = threadIdx.x, lane = tid & 31, w = tid >> 5;
    const int ks = blockIdx.x, mt = blockIdx.y;
    const int mbase = (w >> 1) * 32, nbase = (w & 1) * 32;
    const int kbase = ks * KCHUNK;

    float acc[2][4][4];
#pragma unroll
    for (int i = 0; i < 2; i++)
#pragma unroll
        for (int j = 0; j < 4; j++)
#pragma unroll
            for (int q = 0; q < 4; q++) acc[i][j][q] = 0.f;

    const int r0 = tid >> 4, seg = tid & 15;
    const float* Sp = S + (size_t)(mt * 128 + r0) * NPRE + kbase + seg * 4;
    const uint32_t sxor = (uint32_t)((r0 & 7) << 4);
    uint32_t a_off[8];
#pragma unroll
    for (int i = 0; i < 8; i++)
        a_off[i] = (uint32_t)(r0 + 16 * i) * 128u + (((uint32_t)seg * 8u) ^ sxor);

    uint32_t b_dst[2];
    uint32_t b_row[2];
#pragma unroll
    for (int i = 0; i < 2; i++) {
        uint32_t ch = (uint32_t)tid + 256u * i;   // 0..511
        uint32_t row = ch >> 3, sg = ch & 7;
        b_row[i] = row * 128u + sg * 16u;
        b_dst[i] = row * 128u + ((sg * 16u) ^ ((row & 7u) << 4));
    }

    const uint32_t lrow  = (uint32_t)(lane & 15) * 128u;
    const uint32_t lhalf = (uint32_t)(lane >> 4) * 16u;
    const uint32_t lx    = (uint32_t)(lane & 7) << 4;

    {
        const char* vh = (const char*)g_Vh + (size_t)kbase * 128;
        const char* vl = (const char*)g_Vl + (size_t)kbase * 128;
#pragma unroll
        for (int i = 0; i < 2; i++) {
            cp16(sb + G1_BH + b_dst[i], vh + b_row[i]);
            cp16(sb + G1_BL + b_dst[i], vl + b_row[i]);
        }
        CP_COMMIT();
    }
    float4 ra[8];
#pragma unroll
    for (int i = 0; i < 8; i++) ra[i] = *(const float4*)(Sp + (size_t)i * 16 * NPRE);

#pragma unroll 1
    for (int kt = 0; kt < 8; kt++) {
        const uint32_t cur = (uint32_t)(kt & 1);
        const uint32_t bufb = sb + cur * G1_BUF;
        char* bufc = sm + cur * G1_BUF;

#pragma unroll
        for (int i = 0; i < 8; i++) {
            uint32_t h0, l0, h1, l1;
            split2(ra[i].x, ra[i].y, h0, l0);
            split2(ra[i].z, ra[i].w, h1, l1);
            *(uint2*)(bufc + a_off[i])         = make_uint2(h0, h1);
            *(uint2*)(bufc + G1_AL + a_off[i]) = make_uint2(l0, l1);
        }
        CP_WAIT0();          // B(kt) complete
        __syncthreads();     // all warps done reading buf cur^1

        if (kt + 1 < 8) {
            const char* vh = (const char*)g_Vh + ((size_t)kbase + (kt + 1) * 64) * 128;
            const char* vl = (const char*)g_Vl + ((size_t)kbase + (kt + 1) * 64) * 128;
            const uint32_t obb = sb + (cur ^ 1u) * G1_BUF;
#pragma unroll
            for (int i = 0; i < 2; i++) {
                cp16(obb + G1_BH + b_dst[i], vh + b_row[i]);
                cp16(obb + G1_BL + b_dst[i], vl + b_row[i]);
            }
            CP_COMMIT();
            const float* Sk = Sp + (kt + 1) * 64;
#pragma unroll
            for (int i = 0; i < 8; i++) ra[i] = *(const float4*)(Sk + (size_t)i * 16 * NPRE);
        }

#pragma unroll
        for (int s = 0; s < 4; s++) {
            const uint32_t c = (uint32_t)s * 32u;
            uint32_t ah[2][4], al[2][4];
#pragma unroll
            for (int mi = 0; mi < 2; mi++) {
                uint32_t ad = bufb + (uint32_t)(mbase + mi * 16) * 128u
                            + lrow + ((c + lhalf) ^ lx);
                ldm_x4(ah[mi], ad);
                ldm_x4(al[mi], ad + G1_AL);
            }
#pragma unroll
            for (int t = 0; t < 2; t++) {
                uint32_t bd = bufb + G1_BH + (uint32_t)s * 16u * 128u + lrow
                            + (((uint32_t)(nbase + t * 16) * 2u + lhalf) ^ lx);
                uint32_t bh[4], bl[4];
                ldm_x4_t(bh, bd);
#pragma unroll
                for (int mi = 0; mi < 2; mi++) {
                    mma16816(acc[mi][2 * t],     ah[mi], bh[0], bh[1]);
                    mma16816(acc[mi][2 * t + 1], ah[mi], bh[2], bh[3]);
                    mma16816(acc[mi][2 * t],     al[mi], bh[0], bh[1]);
                    mma16816(acc[mi][2 * t + 1], al[mi], bh[2], bh[3]);
                }
                ldm_x4_t(bl, bd + (G1_BL - G1_BH));
#pragma unroll
                for (int mi = 0; mi < 2; mi++) {
                    mma16816(acc[mi][2 * t],     ah[mi], bl[0], bl[1]);
                    mma16816(acc[mi][2 * t + 1], ah[mi], bl[2], bl[3]);
                }
            }
        }
    }

    float* Zb = g_Zpart + ((size_t)ks * BATCH + mt * 128) * R;
#pragma unroll
    for (int mi = 0; mi < 2; mi++)
#pragma unroll
        for (int nt = 0; nt < 4; nt++) {
            int row = mbase + mi * 16 + (lane >> 2);
            int col = nbase + nt * 8 + 2 * (lane & 3);
            *(float2*)(Zb + (size_t)row * R + col) =
                make_float2(acc[mi][nt][0], acc[mi][nt][1]);
            *(float2*)(Zb + (size_t)(row + 8) * R + col) =
                make_float2(acc[mi][nt][2], acc[mi][nt][3]);
        }
}

// ===========================================================================
// reduce + split: Z = sum_ks Zpart; write packed bf16 hi/lo
// ===========================================================================
__global__ void __launch_bounds__(256, 4)
reduce_split_kernel() {
    const int gid = blockIdx.x * 256 + threadIdx.x;       // pair index
    const float2* p = (const float2*)g_Zpart;
    float sx = 0.f, sy = 0.f;
#pragma unroll
    for (int ks = 0; ks < KSPLIT; ks++) {
        float2 v = p[(size_t)ks * (BATCH * R / 2) + gid];
        sx += v.x;
        sy += v.y;
    }
    uint32_t h, l;
    split2(sx, sy, h, l);
    g_Zh[gid] = h;
    g_Zl[gid] = l;
}

// ===========================================================================
// GEMM2: Y[b][n] = sum_r Z[b][r] * U[n][r].
// Barrier-free mainloop: A(Z) fragments in registers; B fragments loaded
// directly from g_Ufh/g_Ufl with coalesced LDG.128 (no smem, no syncs).
// Persistent over n: grid (74, 4) = 296 blocks = 1 wave at 2 CTAs/SM.
// smem: Zh@0 (16K) Zl@16K  (used only during the one-time A stage)
// ===========================================================================
constexpr int G2_NSTRIDE = 74;
constexpr int G2_NTILES  = NPOST / 64;   // 512
constexpr uint32_t G2_ZL = 16384;
constexpr int G2_SMEM = 32768;

__global__ void __launch_bounds__(256, 2)
g2_kernel(float* __restrict__ Y) {
    extern __shared__ char sm[];
    const uint32_t sb = smem_u32(sm);
    const int tid = threadIdx.x, lane = tid & 31, w = tid >> 5;
    const int bx = blockIdx.x, mt = blockIdx.y;
    const int mbase = (w >> 1) * 32, nhalf = w & 1;

    // one-time Z stage (cp.async) then A fragments -> registers
    {
        const char* zh = (const char*)g_Zh + (size_t)mt * 128 * 128;
        const char* zl = (const char*)g_Zl + (size_t)mt * 128 * 128;
#pragma unroll
        for (int i = 0; i < 4; i++) {
            uint32_t ch = (uint32_t)tid + 256u * i;   // 0..1023
            uint32_t row = ch >> 3, sg = ch & 7;
            uint32_t so = row * 128u + sg * 16u;
            uint32_t dof = row * 128u + ((sg * 16u) ^ ((row & 7u) << 4));
            cp16(sb + dof,         zh + so);
            cp16(sb + G2_ZL + dof, zl + so);
        }
        CP_COMMIT();
    }
    const uint32_t lrow  = (uint32_t)(lane & 15) * 128u;
    const uint32_t lhalf = (uint32_t)(lane >> 4) * 16u;
    const uint32_t lx    = (uint32_t)(lane & 7) << 4;

    CP_WAIT0();
    __syncthreads();

    uint32_t ahr[4][2][4], alr[4][2][4];
#pragma unroll
    for (int s = 0; s < 4; s++) {
        const uint32_t c = (uint32_t)s * 32u;
#pragma unroll
        for (int mi = 0; mi < 2; mi++) {
            uint32_t ad = sb + (uint32_t)(mbase + mi * 16) * 128u
                        + lrow + ((c + lhalf) ^ lx);
            ldm_x4(ahr[s][mi], ad);
            ldm_x4(alr[s][mi], ad + G2_ZL);
        }
    }

    // barrier-free n-loop
#pragma unroll 1
    for (int nt = bx; nt < G2_NTILES; nt += G2_NSTRIDE) {
        float acc[2][4][4];
#pragma unroll
        for (int i = 0; i < 2; i++)
#pragma unroll
            for (int j = 0; j < 4; j++)
#pragma unroll
                for (int q = 0; q < 4; q++) acc[i][j][q] = 0.f;

#pragma unroll
        for (int s = 0; s < 4; s++) {
#pragma unroll
            for (int t = 0; t < 2; t++) {
                const uint32_t n16l = 2u * (uint32_t)nhalf + (uint32_t)t;
                const uint32_t fragid = ((uint32_t)nt * 4u + n16l) * 4u + (uint32_t)s;
                uint4 BH = *(const uint4*)(g_Ufh + fragid * 128u + (uint32_t)lane * 4u);
                uint4 BL = *(const uint4*)(g_Ufl + fragid * 128u + (uint32_t)lane * 4u);
                // reg map: {x,z} = n-group 0 (k lo/hi), {y,w} = n-group 1
#pragma unroll
                for (int mi = 0; mi < 2; mi++) {
                    mma16816(acc[mi][2 * t],     ahr[s][mi], BH.x, BH.z);
                    mma16816(acc[mi][2 * t + 1], ahr[s][mi], BH.y, BH.w);
                    mma16816(acc[mi][2 * t],     alr[s][mi], BH.x, BH.z);
                    mma16816(acc[mi][2 * t + 1], alr[s][mi], BH.y, BH.w);
                    mma16816(acc[mi][2 * t],     ahr[s][mi], BL.x, BL.z);
                    mma16816(acc[mi][2 * t + 1], ahr[s][mi], BL.y, BL.w);
                }
            }
        }

        float* Yb = Y + (size_t)(mt * 128) * NPOST + nt * 64;
        const int nbase = nhalf * 32;
#pragma unroll
        for (int mi = 0; mi < 2; mi++)
#pragma unroll
            for (int ntj = 0; ntj < 4; ntj++) {
                int row = mbase + mi * 16 + (lane >> 2);
                int col = nbase + ntj * 8 + 2 * (lane & 3);
                *(float2*)(Yb + (size_t)row * NPOST + col) =
                    make_float2(acc[mi][ntj][0], acc[mi][ntj][1]);
                *(float2*)(Yb + (size_t)(row + 8) * NPOST + col) =
                    make_float2(acc[mi][ntj][2], acc[mi][ntj][3]);
            }
    }
}

// ===========================================================================
extern "C" void kernel_launch(void* const* d_in, const int* in_sizes, int n_in,
                              void* d_out, int out_size) {
    const float* spikes = (const float*)d_in[0];   // [512, 32768]
    const float* U      = (const float*)d_in[1];   // [32768, 64]
    const float* V      = (const float*)d_in[2];   // [32768, 64]
    float* Y            = (float*)d_out;           // [512, 32768]

    cudaFuncSetAttribute(g1_kernel, cudaFuncAttributeMaxDynamicSharedMemorySize, G1_SMEM);
    cudaFuncSetAttribute(g2_kernel, cudaFuncAttributeMaxDynamicSharedMemorySize, G2_SMEM);

    split_v_kernel<<<NPRE * R / 4 / 256, 256>>>(V);
    prep_ufrag_kernel<<<NPOST / 64, 256>>>(U);
    g1_kernel<<<dim3(KSPLIT, BATCH / 128), 256, G1_SMEM>>>(spikes);
    reduce_split_kernel<<<(BATCH * R / 2) / 256, 256>>>();
    g2_kernel<<<dim3(G2_NSTRIDE, BATCH / 128), 256, G2_SMEM>>>(Y);
}

// round 12
// speedup vs baseline: 1.3666x; 1.3666x over previous
#include <cuda_runtime.h>
#include <cuda_fp16.h>
#include <cstdint>

// y = spikes @ V @ U^T
// spikes: [512, 32768] f32   (d_in[0])
// U     : [32768, 64]  f32   (d_in[1])
// V     : [32768, 64]  f32   (d_in[2])
// mask_* inputs unused. out: [512, 32768] f32
//
// mma.sync fp16 with hi/lo split, TWO products: A_hi*B_hi + A_lo*B_hi.
// fp16's 11-bit mantissa makes the dropped A_hi*B_lo term ~2^-12 relative
// (incoherent) -> rel_err ~3e-4, under the 1e-3 gate.  B sides (V, U) need
// only their fp16-hi halves, halving B traffic and cutting MMAs by 1/3.
// NOTE: cp.async into a shared buffer may only be issued AFTER the
// __syncthreads() that proves all warps finished reading that buffer.

constexpr int BATCH = 512;
constexpr int NPRE  = 32768;
constexpr int NPOST = 32768;
constexpr int R     = 64;

constexpr int KSPLIT = 64;
constexpr int KCHUNK = NPRE / KSPLIT;   // 512

// ---------------- scratch (allocation-free: device globals) ----------------
__device__ __align__(16) float    g_Zpart[KSPLIT * BATCH * R];   // 8 MB
__device__ __align__(16) uint32_t g_Vh[NPRE * R / 2];            // 4 MB (fp16)
__device__ __align__(16) uint32_t g_Uh[NPOST * R / 2];           // 4 MB (fp16)
__device__ __align__(16) uint32_t g_Zh[BATCH * R / 2];           // 64 KB each
__device__ __align__(16) uint32_t g_Zl[BATCH * R / 2];

// ---------------- helpers ---------------------------------------------------
__device__ __forceinline__ uint32_t smem_u32(const void* p) {
    uint32_t a;
    asm("{ .reg .u64 t; cvta.to.shared.u64 t, %1; cvt.u32.u64 %0, t; }"
        : "=r"(a) : "l"(p));
    return a;
}

// fp16 hi of two floats, packed (elem0 in low half)
__device__ __forceinline__ uint32_t pack2h(float x, float y) {
    uint32_t h;
    asm("cvt.rn.f16x2.f32 %0, %1, %2;" : "=r"(h) : "f"(y), "f"(x));
    return h;
}
// fp16 hi/lo split of two floats (elem0 in low half)
__device__ __forceinline__ void split2h(float x, float y, uint32_t& hp, uint32_t& lp) {
    hp = pack2h(x, y);
    __half2 h = *reinterpret_cast<__half2*>(&hp);
    float2 f = __half22float2(h);
    lp = pack2h(x - f.x, y - f.y);
}

__device__ __forceinline__ void cp16(uint32_t dst, const void* src) {
    asm volatile("cp.async.cg.shared.global [%0], [%1], 16;"
                 :: "r"(dst), "l"(src) : "memory");
}
#define CP_COMMIT() asm volatile("cp.async.commit_group;" ::: "memory")
#define CP_WAIT0()  asm volatile("cp.async.wait_group 0;" ::: "memory")

__device__ __forceinline__ void ldm_x4(uint32_t (&r)[4], uint32_t addr) {
    asm volatile("ldmatrix.sync.aligned.m8n8.x4.shared.b16 {%0,%1,%2,%3}, [%4];"
                 : "=r"(r[0]), "=r"(r[1]), "=r"(r[2]), "=r"(r[3]) : "r"(addr));
}
__device__ __forceinline__ void ldm_x4_t(uint32_t (&r)[4], uint32_t addr) {
    asm volatile("ldmatrix.sync.aligned.m8n8.x4.trans.shared.b16 {%0,%1,%2,%3}, [%4];"
                 : "=r"(r[0]), "=r"(r[1]), "=r"(r[2]), "=r"(r[3]) : "r"(addr));
}
__device__ __forceinline__ void mma16816(float (&d)[4], const uint32_t (&a)[4],
                                         uint32_t b0, uint32_t b1) {
    asm volatile("mma.sync.aligned.m16n8k16.row.col.f32.f16.f16.f32 "
                 "{%0,%1,%2,%3}, {%4,%5,%6,%7}, {%8,%9}, {%0,%1,%2,%3};"
                 : "+f"(d[0]), "+f"(d[1]), "+f"(d[2]), "+f"(d[3])
                 : "r"(a[0]), "r"(a[1]), "r"(a[2]), "r"(a[3]), "r"(b0), "r"(b1));
}

// ===========================================================================
// prep: fp16-hi of V and U (packed pairs), row-major [n][64k] = 128B rows
// ===========================================================================
__global__ void __launch_bounds__(256, 4)
split_vu_hi_kernel(const float* __restrict__ V, const float* __restrict__ U) {
    const int gid = blockIdx.x * 256 + threadIdx.x;       // float4 index
    const float4* src = (blockIdx.y == 0) ? (const float4*)V : (const float4*)U;
    uint2* dh = (blockIdx.y == 0) ? (uint2*)g_Vh : (uint2*)g_Uh;
    float4 v = src[gid];
    dh[gid] = make_uint2(pack2h(v.x, v.y), pack2h(v.z, v.w));
}

// ===========================================================================
// GEMM1: Zpart[ks][b][r] = sum_{k in chunk} spikes[b][k] * V[k][r]
// Tile 128(m) x 64(n=R), K-tile 64, 8 k-tiles, double-buffered smem.
// 8 warps = 4m x 2n, warp 32x32.  A split hi/lo in-kernel; B = V_hi only.
// per-buffer smem: Ah[128x64 f16]@0 Al@16K  Bh[64k x 64n]@32K  (40K)
// ===========================================================================
constexpr uint32_t G1_AL = 16384, G1_BH = 32768;
constexpr uint32_t G1_BUF = 40960;
constexpr int G1_SMEM = 81920;

__global__ void __launch_bounds__(256, 2)
g1_kernel(const float* __restrict__ S) {
    extern __shared__ char sm[];
    const uint32_t sb = smem_u32(sm);
    const int tid = threadIdx.x, lane = tid & 31, w = tid >> 5;
    const int ks = blockIdx.x, mt = blockIdx.y;
    const int mbase = (w >> 1) * 32, nbase = (w & 1) * 32;
    const int kbase = ks * KCHUNK;

    float acc[2][4][4];
#pragma unroll
    for (int i = 0; i < 2; i++)
#pragma unroll
        for (int j = 0; j < 4; j++)
#pragma unroll
            for (int q = 0; q < 4; q++) acc[i][j][q] = 0.f;

    // A staging map: row = (tid>>4) + 16i, seg = tid & 15 (float4 units)
    const int r0 = tid >> 4, seg = tid & 15;
    const float* Sp = S + (size_t)(mt * 128 + r0) * NPRE + kbase + seg * 4;
    const uint32_t sxor = (uint32_t)((r0 & 7) << 4);
    uint32_t a_off[8];
#pragma unroll
    for (int i = 0; i < 8; i++)
        a_off[i] = (uint32_t)(r0 + 16 * i) * 128u + (((uint32_t)seg * 8u) ^ sxor);

    // B cp.async map: 2 chunks of 16B per thread (8 KB tile)
    uint32_t b_dst[2], b_row[2];
#pragma unroll
    for (int i = 0; i < 2; i++) {
        uint32_t ch = (uint32_t)tid + 256u * i;   // 0..511
        uint32_t row = ch >> 3, sg = ch & 7;
        b_row[i] = row * 128u + sg * 16u;
        b_dst[i] = row * 128u + ((sg * 16u) ^ ((row & 7u) << 4));
    }

    const uint32_t lrow  = (uint32_t)(lane & 15) * 128u;
    const uint32_t lhalf = (uint32_t)(lane >> 4) * 16u;
    const uint32_t lx    = (uint32_t)(lane & 7) << 4;

    // prologue: issue B(0) into buf0; prefetch A(0) regs
    {
        const char* vh = (const char*)g_Vh + (size_t)kbase * 128;
#pragma unroll
        for (int i = 0; i < 2; i++)
            cp16(sb + G1_BH + b_dst[i], vh + b_row[i]);
        CP_COMMIT();
    }
    float4 ra[8];
#pragma unroll
    for (int i = 0; i < 8; i++) ra[i] = *(const float4*)(Sp + (size_t)i * 16 * NPRE);

#pragma unroll 1
    for (int kt = 0; kt < 8; kt++) {
        const uint32_t cur = (uint32_t)(kt & 1);
        const uint32_t bufb = sb + cur * G1_BUF;
        char* bufc = sm + cur * G1_BUF;

        // store A(kt) hi/lo into buf cur
#pragma unroll
        for (int i = 0; i < 8; i++) {
            uint32_t h0, l0, h1, l1;
            split2h(ra[i].x, ra[i].y, h0, l0);
            split2h(ra[i].z, ra[i].w, h1, l1);
            *(uint2*)(bufc + a_off[i])         = make_uint2(h0, h1);
            *(uint2*)(bufc + G1_AL + a_off[i]) = make_uint2(l0, l1);
        }
        CP_WAIT0();          // B(kt) complete
        __syncthreads();     // all warps done reading buf cur^1

        // safe to issue B(kt+1) into the other buffer; prefetch A(kt+1)
        if (kt + 1 < 8) {
            const char* vh = (const char*)g_Vh + ((size_t)kbase + (kt + 1) * 64) * 128;
            const uint32_t obb = sb + (cur ^ 1u) * G1_BUF;
#pragma unroll
            for (int i = 0; i < 2; i++)
                cp16(obb + G1_BH + b_dst[i], vh + b_row[i]);
            CP_COMMIT();
            const float* Sk = Sp + (kt + 1) * 64;
#pragma unroll
            for (int i = 0; i < 8; i++) ra[i] = *(const float4*)(Sk + (size_t)i * 16 * NPRE);
        }

        // mma on buf cur: acc += Ah*Bh + Al*Bh
#pragma unroll
        for (int s = 0; s < 4; s++) {
            const uint32_t c = (uint32_t)s * 32u;
            uint32_t ah[2][4], al[2][4];
#pragma unroll
            for (int mi = 0; mi < 2; mi++) {
                uint32_t ad = bufb + (uint32_t)(mbase + mi * 16) * 128u
                            + lrow + ((c + lhalf) ^ lx);
                ldm_x4(ah[mi], ad);
                ldm_x4(al[mi], ad + G1_AL);
            }
#pragma unroll
            for (int t = 0; t < 2; t++) {
                uint32_t bd = bufb + G1_BH + (uint32_t)s * 16u * 128u + lrow
                            + (((uint32_t)(nbase + t * 16) * 2u + lhalf) ^ lx);
                uint32_t bh[4];
                ldm_x4_t(bh, bd);
#pragma unroll
                for (int mi = 0; mi < 2; mi++) {
                    mma16816(acc[mi][2 * t],     ah[mi], bh[0], bh[1]);
                    mma16816(acc[mi][2 * t + 1], ah[mi], bh[2], bh[3]);
                    mma16816(acc[mi][2 * t],     al[mi], bh[0], bh[1]);
                    mma16816(acc[mi][2 * t + 1], al[mi], bh[2], bh[3]);
                }
            }
        }
    }

    // epilogue -> Zpart
    float* Zb = g_Zpart + ((size_t)ks * BATCH + mt * 128) * R;
#pragma unroll
    for (int mi = 0; mi < 2; mi++)
#pragma unroll
        for (int nt = 0; nt < 4; nt++) {
            int row = mbase + mi * 16 + (lane >> 2);
            int col = nbase + nt * 8 + 2 * (lane & 3);
            *(float2*)(Zb + (size_t)row * R + col) =
                make_float2(acc[mi][nt][0], acc[mi][nt][1]);
            *(float2*)(Zb + (size_t)(row + 8) * R + col) =
                make_float2(acc[mi][nt][2], acc[mi][nt][3]);
        }
}

// ===========================================================================
// reduce + split: Z = sum_ks Zpart; write packed fp16 hi/lo.
// 256 blocks; 4 threads cooperate per output pair via smem (fixed order).
// ===========================================================================
__global__ void __launch_bounds__(256, 4)
reduce_split_kernel() {
    __shared__ float2 s[4][64];
    const int tid = threadIdx.x;
    const int sub = tid >> 6, li = tid & 63;
    const int gid = blockIdx.x * 64 + li;                 // pair index
    const float2* p = (const float2*)g_Zpart;
    float sx = 0.f, sy = 0.f;
#pragma unroll
    for (int k = 0; k < 16; k++) {
        float2 v = p[(size_t)(sub * 16 + k) * (BATCH * R / 2) + gid];
        sx += v.x;
        sy += v.y;
    }
    s[sub][li] = make_float2(sx, sy);
    __syncthreads();
    if (sub == 0) {
        float2 a = s[0][li], b = s[1][li], c = s[2][li], d = s[3][li];
        float fx = (a.x + b.x) + (c.x + d.x);
        float fy = (a.y + b.y) + (c.y + d.y);
        uint32_t h, l;
        split2h(fx, fy, h, l);
        g_Zh[gid] = h;
        g_Zl[gid] = l;
    }
}

// ===========================================================================
// GEMM2: Y[b][n] = sum_r Z[b][r] * U[n][r].
// Persistent over n: A(Z) fragments register-resident (hi+lo), B = U_hi only,
// double-buffered smem.  Grid (74, 4) = 296 blocks = 1 wave at 2 CTAs/SM.
// smem: Zh@0 (16K) Zl@16K | B buf0 @32K (8K) | buf1 @40K (8K)
// ===========================================================================
constexpr int G2_NSTRIDE = 74;
constexpr int G2_NTILES  = NPOST / 64;   // 512
constexpr uint32_t G2_ZL = 16384, G2_B0 = 32768;
constexpr int G2_SMEM = 49152;

__global__ void __launch_bounds__(256, 2)
g2_kernel(float* __restrict__ Y) {
    extern __shared__ char sm[];
    const uint32_t sb = smem_u32(sm);
    const int tid = threadIdx.x, lane = tid & 31, w = tid >> 5;
    const int bx = blockIdx.x, mt = blockIdx.y;
    const int mbase = (w >> 1) * 32, nhalf = w & 1;

    // stage Z (mt) hi/lo: 4 chunks of 16B per half per thread
    {
        const char* zh = (const char*)g_Zh + (size_t)mt * 128 * 128;
        const char* zl = (const char*)g_Zl + (size_t)mt * 128 * 128;
#pragma unroll
        for (int i = 0; i < 4; i++) {
            uint32_t ch = (uint32_t)tid + 256u * i;   // 0..1023
            uint32_t row = ch >> 3, sg = ch & 7;
            uint32_t so = row * 128u + sg * 16u;
            uint32_t dof = row * 128u + ((sg * 16u) ^ ((row & 7u) << 4));
            cp16(sb + dof,         zh + so);
            cp16(sb + G2_ZL + dof, zl + so);
        }
        CP_COMMIT();
    }

    // B cp.async map: 2 chunks of 16B per thread (8 KB tile)
    uint32_t b_dst[2], b_src[2];
#pragma unroll
    for (int i = 0; i < 2; i++) {
        uint32_t ch = (uint32_t)tid + 256u * i;       // 0..511
        uint32_t row = ch >> 3, sg = ch & 7;
        b_src[i] = row * 128u + sg * 16u;
        b_dst[i] = row * 128u + ((sg * 16u) ^ ((row & 7u) << 4));
    }
    // issue B(first n-tile) into buf0
    {
        const char* uh = (const char*)g_Uh + (size_t)bx * 64 * 128;
#pragma unroll
        for (int i = 0; i < 2; i++)
            cp16(sb + G2_B0 + b_dst[i], uh + b_src[i]);
        CP_COMMIT();
    }

    const uint32_t lrow  = (uint32_t)(lane & 15) * 128u;
    const uint32_t lhalf = (uint32_t)(lane >> 4) * 16u;
    const uint32_t lx    = (uint32_t)(lane & 7) << 4;

    CP_WAIT0();          // both groups done (Z staged; B(first) also done)
    __syncthreads();

    // A fragments -> registers: 32 hi + 32 lo
    uint32_t ahr[4][2][4], alr[4][2][4];
#pragma unroll
    for (int s = 0; s < 4; s++) {
        const uint32_t c = (uint32_t)s * 32u;
#pragma unroll
        for (int mi = 0; mi < 2; mi++) {
            uint32_t ad = sb + (uint32_t)(mbase + mi * 16) * 128u
                        + lrow + ((c + lhalf) ^ lx);
            ldm_x4(ahr[s][mi], ad);
            ldm_x4(alr[s][mi], ad + G2_ZL);
        }
    }

    int it = 0;
#pragma unroll 1
    for (int nt = bx; nt < G2_NTILES; nt += G2_NSTRIDE, it++) {
        const uint32_t bufb = G2_B0 + (uint32_t)(it & 1) * 8192u;

        CP_WAIT0();          // B(nt) complete
        __syncthreads();     // all warps done reading the other buffer

        // safe to refill the other buffer now
        if (nt + G2_NSTRIDE < G2_NTILES) {
            const uint32_t ob = sb + G2_B0 + (uint32_t)((it + 1) & 1) * 8192u;
            const char* uh = (const char*)g_Uh + (size_t)(nt + G2_NSTRIDE) * 64 * 128;
#pragma unroll
            for (int i = 0; i < 2; i++)
                cp16(ob + b_dst[i], uh + b_src[i]);
            CP_COMMIT();
        }

        float acc[2][4][4];
#pragma unroll
        for (int i = 0; i < 2; i++)
#pragma unroll
            for (int j = 0; j < 4; j++)
#pragma unroll
                for (int q = 0; q < 4; q++) acc[i][j][q] = 0.f;

#pragma unroll
        for (int s = 0; s < 4; s++) {
            const uint32_t c = (uint32_t)s * 32u;
#pragma unroll
            for (int t = 0; t < 2; t++) {
                uint32_t bd = sb + bufb + (uint32_t)(nhalf * 32 + t * 16) * 128u
                            + lrow + ((c + lhalf) ^ lx);
                uint32_t bh[4];
                ldm_x4(bh, bd);
                // reg map: {r0,r2} = n-group 0 (k lo/hi), {r1,r3} = n-group 1
#pragma unroll
                for (int mi = 0; mi < 2; mi++) {
                    mma16816(acc[mi][2 * t],     ahr[s][mi], bh[0], bh[2]);
                    mma16816(acc[mi][2 * t + 1], ahr[s][mi], bh[1], bh[3]);
                    mma16816(acc[mi][2 * t],     alr[s][mi], bh[0], bh[2]);
                    mma16816(acc[mi][2 * t + 1], alr[s][mi], bh[1], bh[3]);
                }
            }
        }

        // epilogue -> Y for this n-tile
        float* Yb = Y + (size_t)(mt * 128) * NPOST + nt * 64;
        const int nbase = nhalf * 32;
#pragma unroll
        for (int mi = 0; mi < 2; mi++)
#pragma unroll
            for (int ntj = 0; ntj < 4; ntj++) {
                int row = mbase + mi * 16 + (lane >> 2);
                int col = nbase + ntj * 8 + 2 * (lane & 3);
                *(float2*)(Yb + (size_t)row * NPOST + col) =
                    make_float2(acc[mi][ntj][0], acc[mi][ntj][1]);
                *(float2*)(Yb + (size_t)(row + 8) * NPOST + col) =
                    make_float2(acc[mi][ntj][2], acc[mi][ntj][3]);
            }
    }
}

// ===========================================================================
extern "C" void kernel_launch(void* const* d_in, const int* in_sizes, int n_in,
                              void* d_out, int out_size) {
    const float* spikes = (const float*)d_in[0];   // [512, 32768]
    const float* U      = (const float*)d_in[1];   // [32768, 64]
    const float* V      = (const float*)d_in[2];   // [32768, 64]
    float* Y            = (float*)d_out;           // [512, 32768]

    cudaFuncSetAttribute(g1_kernel, cudaFuncAttributeMaxDynamicSharedMemorySize, G1_SMEM);
    cudaFuncSetAttribute(g2_kernel, cudaFuncAttributeMaxDynamicSharedMemorySize, G2_SMEM);

    split_vu_hi_kernel<<<dim3(NPRE * R / 4 / 256, 2), 256>>>(V, U);
    g1_kernel<<<dim3(KSPLIT, BATCH / 128), 256, G1_SMEM>>>(spikes);
    reduce_split_kernel<<<(BATCH * R / 2) / 64, 256>>>();
    g2_kernel<<<dim3(G2_NSTRIDE, BATCH / 128), 256, G2_SMEM>>>(Y);
}

// round 13
// speedup vs baseline: 1.3752x; 1.0063x over previous
#include <cuda_runtime.h>
#include <cuda_fp16.h>
#include <cstdint>

// y = spikes @ V @ U^T
// spikes: [512, 32768] f32   (d_in[0])
// U     : [32768, 64]  f32   (d_in[1])
// V     : [32768, 64]  f32   (d_in[2])
// mask_* inputs unused. out: [512, 32768] f32
//
// mma.sync fp16 with hi/lo split, TWO products: A_hi*B_hi + A_lo*B_hi.
// MMA ordering: all hi products (8 independent accs) then all lo products,
// so every RAW accumulator pair has >=8 instructions between (HMMA lat ~30).
// NOTE: cp.async into a shared buffer may only be issued AFTER the
// __syncthreads() that proves all warps finished reading that buffer.

constexpr int BATCH = 512;
constexpr int NPRE  = 32768;
constexpr int NPOST = 32768;
constexpr int R     = 64;

constexpr int KSPLIT = 64;
constexpr int KCHUNK = NPRE / KSPLIT;   // 512

// ---------------- scratch (allocation-free: device globals) ----------------
__device__ __align__(16) float    g_Zpart[KSPLIT * BATCH * R];   // 8 MB
__device__ __align__(16) uint32_t g_Vh[NPRE * R / 2];            // 4 MB (fp16)
__device__ __align__(16) uint32_t g_Uh[NPOST * R / 2];           // 4 MB (fp16)
__device__ __align__(16) uint32_t g_Zh[BATCH * R / 2];           // 64 KB each
__device__ __align__(16) uint32_t g_Zl[BATCH * R / 2];

// ---------------- helpers ---------------------------------------------------
__device__ __forceinline__ uint32_t smem_u32(const void* p) {
    uint32_t a;
    asm("{ .reg .u64 t; cvta.to.shared.u64 t, %1; cvt.u32.u64 %0, t; }"
        : "=r"(a) : "l"(p));
    return a;
}

// fp16 hi of two floats, packed (elem0 in low half)
__device__ __forceinline__ uint32_t pack2h(float x, float y) {
    uint32_t h;
    asm("cvt.rn.f16x2.f32 %0, %1, %2;" : "=r"(h) : "f"(y), "f"(x));
    return h;
}
// fp16 hi/lo split of two floats (elem0 in low half)
__device__ __forceinline__ void split2h(float x, float y, uint32_t& hp, uint32_t& lp) {
    hp = pack2h(x, y);
    __half2 h = *reinterpret_cast<__half2*>(&hp);
    float2 f = __half22float2(h);
    lp = pack2h(x - f.x, y - f.y);
}

__device__ __forceinline__ void cp16(uint32_t dst, const void* src) {
    asm volatile("cp.async.cg.shared.global [%0], [%1], 16;"
                 :: "r"(dst), "l"(src) : "memory");
}
#define CP_COMMIT() asm volatile("cp.async.commit_group;" ::: "memory")
#define CP_WAIT0()  asm volatile("cp.async.wait_group 0;" ::: "memory")

__device__ __forceinline__ void ldm_x4(uint32_t (&r)[4], uint32_t addr) {
    asm volatile("ldmatrix.sync.aligned.m8n8.x4.shared.b16 {%0,%1,%2,%3}, [%4];"
                 : "=r"(r[0]), "=r"(r[1]), "=r"(r[2]), "=r"(r[3]) : "r"(addr));
}
__device__ __forceinline__ void ldm_x4_t(uint32_t (&r)[4], uint32_t addr) {
    asm volatile("ldmatrix.sync.aligned.m8n8.x4.trans.shared.b16 {%0,%1,%2,%3}, [%4];"
                 : "=r"(r[0]), "=r"(r[1]), "=r"(r[2]), "=r"(r[3]) : "r"(addr));
}
__device__ __forceinline__ void mma16816(float (&d)[4], const uint32_t (&a)[4],
                                         uint32_t b0, uint32_t b1) {
    asm volatile("mma.sync.aligned.m16n8k16.row.col.f32.f16.f16.f32 "
                 "{%0,%1,%2,%3}, {%4,%5,%6,%7}, {%8,%9}, {%0,%1,%2,%3};"
                 : "+f"(d[0]), "+f"(d[1]), "+f"(d[2]), "+f"(d[3])
                 : "r"(a[0]), "r"(a[1]), "r"(a[2]), "r"(a[3]), "r"(b0), "r"(b1));
}

// ===========================================================================
// prep: fp16-hi of V and U (packed pairs), row-major [n][64k] = 128B rows
// ===========================================================================
__global__ void __launch_bounds__(256, 4)
split_vu_hi_kernel(const float* __restrict__ V, const float* __restrict__ U) {
    const int gid = blockIdx.x * 256 + threadIdx.x;       // float4 index
    const float4* src = (blockIdx.y == 0) ? (const float4*)V : (const float4*)U;
    uint2* dh = (blockIdx.y == 0) ? (uint2*)g_Vh : (uint2*)g_Uh;
    float4 v = src[gid];
    dh[gid] = make_uint2(pack2h(v.x, v.y), pack2h(v.z, v.w));
}

// ===========================================================================
// GEMM1: Zpart[ks][b][r] = sum_{k in chunk} spikes[b][k] * V[k][r]
// Tile 128(m) x 64(n=R), K-tile 64, 8 k-tiles, double-buffered smem.
// 8 warps = 4m x 2n, warp 32x32.  A split hi/lo in-kernel; B = V_hi only.
// per-buffer smem: Ah[128x64 f16]@0 Al@16K  Bh[64k x 64n]@32K  (40K)
// ===========================================================================
constexpr uint32_t G1_AL = 16384, G1_BH = 32768;
constexpr uint32_t G1_BUF = 40960;
constexpr int G1_SMEM = 81920;

__global__ void __launch_bounds__(256, 2)
g1_kernel(const float* __restrict__ S) {
    extern __shared__ char sm[];
    const uint32_t sb = smem_u32(sm);
    const int tid = threadIdx.x, lane = tid & 31, w = tid >> 5;
    const int ks = blockIdx.x, mt = blockIdx.y;
    const int mbase = (w >> 1) * 32, nbase = (w & 1) * 32;
    const int kbase = ks * KCHUNK;

    float acc[2][4][4];
#pragma unroll
    for (int i = 0; i < 2; i++)
#pragma unroll
        for (int j = 0; j < 4; j++)
#pragma unroll
            for (int q = 0; q < 4; q++) acc[i][j][q] = 0.f;

    // A staging map: row = (tid>>4) + 16i, seg = tid & 15 (float4 units)
    const int r0 = tid >> 4, seg = tid & 15;
    const float* Sp = S + (size_t)(mt * 128 + r0) * NPRE + kbase + seg * 4;
    const uint32_t sxor = (uint32_t)((r0 & 7) << 4);
    uint32_t a_off[8];
#pragma unroll
    for (int i = 0; i < 8; i++)
        a_off[i] = (uint32_t)(r0 + 16 * i) * 128u + (((uint32_t)seg * 8u) ^ sxor);

    // B cp.async map: 2 chunks of 16B per thread (8 KB tile)
    uint32_t b_dst[2], b_row[2];
#pragma unroll
    for (int i = 0; i < 2; i++) {
        uint32_t ch = (uint32_t)tid + 256u * i;   // 0..511
        uint32_t row = ch >> 3, sg = ch & 7;
        b_row[i] = row * 128u + sg * 16u;
        b_dst[i] = row * 128u + ((sg * 16u) ^ ((row & 7u) << 4));
    }

    const uint32_t lrow  = (uint32_t)(lane & 15) * 128u;
    const uint32_t lhalf = (uint32_t)(lane >> 4) * 16u;
    const uint32_t lx    = (uint32_t)(lane & 7) << 4;

    // prologue: issue B(0) into buf0; prefetch A(0) regs
    {
        const char* vh = (const char*)g_Vh + (size_t)kbase * 128;
#pragma unroll
        for (int i = 0; i < 2; i++)
            cp16(sb + G1_BH + b_dst[i], vh + b_row[i]);
        CP_COMMIT();
    }
    float4 ra[8];
#pragma unroll
    for (int i = 0; i < 8; i++) ra[i] = *(const float4*)(Sp + (size_t)i * 16 * NPRE);

#pragma unroll 1
    for (int kt = 0; kt < 8; kt++) {
        const uint32_t cur = (uint32_t)(kt & 1);
        const uint32_t bufb = sb + cur * G1_BUF;
        char* bufc = sm + cur * G1_BUF;

        // store A(kt) hi/lo into buf cur
#pragma unroll
        for (int i = 0; i < 8; i++) {
            uint32_t h0, l0, h1, l1;
            split2h(ra[i].x, ra[i].y, h0, l0);
            split2h(ra[i].z, ra[i].w, h1, l1);
            *(uint2*)(bufc + a_off[i])         = make_uint2(h0, h1);
            *(uint2*)(bufc + G1_AL + a_off[i]) = make_uint2(l0, l1);
        }
        CP_WAIT0();          // B(kt) complete
        __syncthreads();     // all warps done reading buf cur^1

        // safe to issue B(kt+1) into the other buffer; prefetch A(kt+1)
        if (kt + 1 < 8) {
            const char* vh = (const char*)g_Vh + ((size_t)kbase + (kt + 1) * 64) * 128;
            const uint32_t obb = sb + (cur ^ 1u) * G1_BUF;
#pragma unroll
            for (int i = 0; i < 2; i++)
                cp16(obb + G1_BH + b_dst[i], vh + b_row[i]);
            CP_COMMIT();
            const float* Sk = Sp + (kt + 1) * 64;
#pragma unroll
            for (int i = 0; i < 8; i++) ra[i] = *(const float4*)(Sk + (size_t)i * 16 * NPRE);
        }

        // mma on buf cur: acc += Ah*Bh (8 indep) then Al*Bh (8 indep)
#pragma unroll
        for (int s = 0; s < 4; s++) {
            const uint32_t c = (uint32_t)s * 32u;
            uint32_t ah[2][4], al[2][4], bh[2][4];
#pragma unroll
            for (int mi = 0; mi < 2; mi++) {
                uint32_t ad = bufb + (uint32_t)(mbase + mi * 16) * 128u
                            + lrow + ((c + lhalf) ^ lx);
                ldm_x4(ah[mi], ad);
                ldm_x4(al[mi], ad + G1_AL);
            }
#pragma unroll
            for (int t = 0; t < 2; t++) {
                uint32_t bd = bufb + G1_BH + (uint32_t)s * 16u * 128u + lrow
                            + (((uint32_t)(nbase + t * 16) * 2u + lhalf) ^ lx);
                ldm_x4_t(bh[t], bd);
            }
            // 8 hi MMAs (independent accumulators)
#pragma unroll
            for (int t = 0; t < 2; t++)
#pragma unroll
                for (int mi = 0; mi < 2; mi++) {
                    mma16816(acc[mi][2 * t],     ah[mi], bh[t][0], bh[t][1]);
                    mma16816(acc[mi][2 * t + 1], ah[mi], bh[t][2], bh[t][3]);
                }
            // 8 lo MMAs (each RAW partner is 8 instructions back)
#pragma unroll
            for (int t = 0; t < 2; t++)
#pragma unroll
                for (int mi = 0; mi < 2; mi++) {
                    mma16816(acc[mi][2 * t],     al[mi], bh[t][0], bh[t][1]);
                    mma16816(acc[mi][2 * t + 1], al[mi], bh[t][2], bh[t][3]);
                }
        }
    }

    // epilogue -> Zpart
    float* Zb = g_Zpart + ((size_t)ks * BATCH + mt * 128) * R;
#pragma unroll
    for (int mi = 0; mi < 2; mi++)
#pragma unroll
        for (int nt = 0; nt < 4; nt++) {
            int row = mbase + mi * 16 + (lane >> 2);
            int col = nbase + nt * 8 + 2 * (lane & 3);
            *(float2*)(Zb + (size_t)row * R + col) =
                make_float2(acc[mi][nt][0], acc[mi][nt][1]);
            *(float2*)(Zb + (size_t)(row + 8) * R + col) =
                make_float2(acc[mi][nt][2], acc[mi][nt][3]);
        }
}

// ===========================================================================
// reduce + split: Z = sum_ks Zpart; write packed fp16 hi/lo.
// 256 blocks; 4 threads cooperate per output pair via smem (fixed order).
// ===========================================================================
__global__ void __launch_bounds__(256, 4)
reduce_split_kernel() {
    __shared__ float2 s[4][64];
    const int tid = threadIdx.x;
    const int sub = tid >> 6, li = tid & 63;
    const int gid = blockIdx.x * 64 + li;                 // pair index
    const float2* p = (const float2*)g_Zpart;
    float sx = 0.f, sy = 0.f;
#pragma unroll
    for (int k = 0; k < 16; k++) {
        float2 v = p[(size_t)(sub * 16 + k) * (BATCH * R / 2) + gid];
        sx += v.x;
        sy += v.y;
    }
    s[sub][li] = make_float2(sx, sy);
    __syncthreads();
    if (sub == 0) {
        float2 a = s[0][li], b = s[1][li], c = s[2][li], d = s[3][li];
        float fx = (a.x + b.x) + (c.x + d.x);
        float fy = (a.y + b.y) + (c.y + d.y);
        uint32_t h, l;
        split2h(fx, fy, h, l);
        g_Zh[gid] = h;
        g_Zl[gid] = l;
    }
}

// ===========================================================================
// GEMM2: Y[b][n] = sum_r Z[b][r] * U[n][r].
// Persistent over n: A(Z) fragments register-resident (hi+lo), B = U_hi only,
// double-buffered smem.  Grid (74, 4) = 296 blocks = 1 wave at 2 CTAs/SM.
// smem: Zh@0 (16K) Zl@16K | B buf0 @32K (8K) | buf1 @40K (8K)
// ===========================================================================
constexpr int G2_NSTRIDE = 74;
constexpr int G2_NTILES  = NPOST / 64;   // 512
constexpr uint32_t G2_ZL = 16384, G2_B0 = 32768;
constexpr int G2_SMEM = 49152;

__global__ void __launch_bounds__(256, 2)
g2_kernel(float* __restrict__ Y) {
    extern __shared__ char sm[];
    const uint32_t sb = smem_u32(sm);
    const int tid = threadIdx.x, lane = tid & 31, w = tid >> 5;
    const int bx = blockIdx.x, mt = blockIdx.y;
    const int mbase = (w >> 1) * 32, nhalf = w & 1;

    // stage Z (mt) hi/lo: 4 chunks of 16B per half per thread
    {
        const char* zh = (const char*)g_Zh + (size_t)mt * 128 * 128;
        const char* zl = (const char*)g_Zl + (size_t)mt * 128 * 128;
#pragma unroll
        for (int i = 0; i < 4; i++) {
            uint32_t ch = (uint32_t)tid + 256u * i;   // 0..1023
            uint32_t row = ch >> 3, sg = ch & 7;
            uint32_t so = row * 128u + sg * 16u;
            uint32_t dof = row * 128u + ((sg * 16u) ^ ((row & 7u) << 4));
            cp16(sb + dof,         zh + so);
            cp16(sb + G2_ZL + dof, zl + so);
        }
        CP_COMMIT();
    }

    // B cp.async map: 2 chunks of 16B per thread (8 KB tile)
    uint32_t b_dst[2], b_src[2];
#pragma unroll
    for (int i = 0; i < 2; i++) {
        uint32_t ch = (uint32_t)tid + 256u * i;       // 0..511
        uint32_t row = ch >> 3, sg = ch & 7;
        b_src[i] = row * 128u + sg * 16u;
        b_dst[i] = row * 128u + ((sg * 16u) ^ ((row & 7u) << 4));
    }
    // issue B(first n-tile) into buf0
    {
        const char* uh = (const char*)g_Uh + (size_t)bx * 64 * 128;
#pragma unroll
        for (int i = 0; i < 2; i++)
            cp16(sb + G2_B0 + b_dst[i], uh + b_src[i]);
        CP_COMMIT();
    }

    const uint32_t lrow  = (uint32_t)(lane & 15) * 128u;
    const uint32_t lhalf = (uint32_t)(lane >> 4) * 16u;
    const uint32_t lx    = (uint32_t)(lane & 7) << 4;

    CP_WAIT0();          // both groups done (Z staged; B(first) also done)
    __syncthreads();

    // A fragments -> registers: 32 hi + 32 lo
    uint32_t ahr[4][2][4], alr[4][2][4];
#pragma unroll
    for (int s = 0; s < 4; s++) {
        const uint32_t c = (uint32_t)s * 32u;
#pragma unroll
        for (int mi = 0; mi < 2; mi++) {
            uint32_t ad = sb + (uint32_t)(mbase + mi * 16) * 128u
                        + lrow + ((c + lhalf) ^ lx);
            ldm_x4(ahr[s][mi], ad);
            ldm_x4(alr[s][mi], ad + G2_ZL);
        }
    }

    int it = 0;
#pragma unroll 1
    for (int nt = bx; nt < G2_NTILES; nt += G2_NSTRIDE, it++) {
        const uint32_t bufb = G2_B0 + (uint32_t)(it & 1) * 8192u;

        CP_WAIT0();          // B(nt) complete
        __syncthreads();     // all warps done reading the other buffer

        // safe to refill the other buffer now
        if (nt + G2_NSTRIDE < G2_NTILES) {
            const uint32_t ob = sb + G2_B0 + (uint32_t)((it + 1) & 1) * 8192u;
            const char* uh = (const char*)g_Uh + (size_t)(nt + G2_NSTRIDE) * 64 * 128;
#pragma unroll
            for (int i = 0; i < 2; i++)
                cp16(ob + b_dst[i], uh + b_src[i]);
            CP_COMMIT();
        }

        float acc[2][4][4];
#pragma unroll
        for (int i = 0; i < 2; i++)
#pragma unroll
            for (int j = 0; j < 4; j++)
#pragma unroll
                for (int q = 0; q < 4; q++) acc[i][j][q] = 0.f;

#pragma unroll
        for (int s = 0; s < 4; s++) {
            const uint32_t c = (uint32_t)s * 32u;
            uint32_t bh[2][4];
#pragma unroll
            for (int t = 0; t < 2; t++) {
                uint32_t bd = sb + bufb + (uint32_t)(nhalf * 32 + t * 16) * 128u
                            + lrow + ((c + lhalf) ^ lx);
                ldm_x4(bh[t], bd);
            }
            // 8 hi MMAs (independent accumulators)
            // reg map: {r0,r2} = n-group 0 (k lo/hi), {r1,r3} = n-group 1
#pragma unroll
            for (int t = 0; t < 2; t++)
#pragma unroll
                for (int mi = 0; mi < 2; mi++) {
                    mma16816(acc[mi][2 * t],     ahr[s][mi], bh[t][0], bh[t][2]);
                    mma16816(acc[mi][2 * t + 1], ahr[s][mi], bh[t][1], bh[t][3]);
                }
            // 8 lo MMAs (each RAW partner is 8 instructions back)
#pragma unroll
            for (int t = 0; t < 2; t++)
#pragma unroll
                for (int mi = 0; mi < 2; mi++) {
                    mma16816(acc[mi][2 * t],     alr[s][mi], bh[t][0], bh[t][2]);
                    mma16816(acc[mi][2 * t + 1], alr[s][mi], bh[t][1], bh[t][3]);
                }
        }

        // epilogue -> Y for this n-tile
        float* Yb = Y + (size_t)(mt * 128) * NPOST + nt * 64;
        const int nbase = nhalf * 32;
#pragma unroll
        for (int mi = 0; mi < 2; mi++)
#pragma unroll
            for (int ntj = 0; ntj < 4; ntj++) {
                int row = mbase + mi * 16 + (lane >> 2);
                int col = nbase + ntj * 8 + 2 * (lane & 3);
                *(float2*)(Yb + (size_t)row * NPOST + col) =
                    make_float2(acc[mi][ntj][0], acc[mi][ntj][1]);
                *(float2*)(Yb + (size_t)(row + 8) * NPOST + col) =
                    make_float2(acc[mi][ntj][2], acc[mi][ntj][3]);
            }
    }
}

// ===========================================================================
extern "C" void kernel_launch(void* const* d_in, const int* in_sizes, int n_in,
                              void* d_out, int out_size) {
    const float* spikes = (const float*)d_in[0];   // [512, 32768]
    const float* U      = (const float*)d_in[1];   // [32768, 64]
    const float* V      = (const float*)d_in[2];   // [32768, 64]
    float* Y            = (float*)d_out;           // [512, 32768]

    cudaFuncSetAttribute(g1_kernel, cudaFuncAttributeMaxDynamicSharedMemorySize, G1_SMEM);
    cudaFuncSetAttribute(g2_kernel, cudaFuncAttributeMaxDynamicSharedMemorySize, G2_SMEM);

    split_vu_hi_kernel<<<dim3(NPRE * R / 4 / 256, 2), 256>>>(V, U);
    g1_kernel<<<dim3(KSPLIT, BATCH / 128), 256, G1_SMEM>>>(spikes);
    reduce_split_kernel<<<(BATCH * R / 2) / 64, 256>>>();
    g2_kernel<<<dim3(G2_NSTRIDE, BATCH / 128), 256, G2_SMEM>>>(Y);
}